// round 3
// baseline (speedup 1.0000x reference)
#include <cuda_runtime.h>

// ---------------------------------------------------------------------------
// EncoderSRNN: stack-augmented RNN, T=127 sequential steps, batch 32.
// One CTA per batch element (fully independent). Weights pre-transposed into
// __device__ scratch for coalesced GEMV loads. Buffer recurrence replaced by
// a commuting-shift coefficient vector. Stack + embeddings in shared memory.
// ---------------------------------------------------------------------------

#define T_STEPS 127
#define NSEQ    64
#define BSZ     32
#define HDIM    256
#define EDIM    256
#define SDIM    128
#define SSZ     128

// Output layout: (outputs[T,B,H], hid[B,H], stack[B,SSZ,SDIM], acts[T,B,2], top[T,B,SDIM])
#define OUT_OUTPUTS 0
#define OUT_HID     (T_STEPS*BSZ*HDIM)               // 1040384
#define OUT_STACK   (OUT_HID + BSZ*HDIM)             // 1048576
#define OUT_ACTS    (OUT_STACK + BSZ*SSZ*SDIM)       // 1572864
#define OUT_TOP     (OUT_ACTS + T_STEPS*BSZ*2)       // 1580992

// Transposed weights: WT[k][o] = W[o][k]
__device__ __align__(16) float g_WTe[256*256];  // W_e2h^T  (EDIM x HDIM)
__device__ __align__(16) float g_WTs[256*256];  // W_s2h^T  (2*SDIM x HDIM)
__device__ __align__(16) float g_WTh[256*256];  // W_h2h^T  (HDIM x HDIM)
__device__ __align__(16) float g_WTp[256*128];  // W_h2s^T  (HDIM x SDIM)
__device__ __align__(16) float g_WTu[256*128];  // W_s2u^T  (2*SDIM x SDIM)

__global__ void prep_kernel(const float* __restrict__ We, const float* __restrict__ Ws,
                            const float* __restrict__ Wh, const float* __restrict__ Wp,
                            const float* __restrict__ Wu) {
    int id = blockIdx.x * blockDim.x + threadIdx.x;   // 262144 total
    if (id < 65536)        { int k = id >> 8,           o = id & 255;  g_WTe[id]          = We[o*256 + k]; }
    else if (id < 131072)  { int r = id - 65536,  k = r >> 8, o = r & 255; g_WTs[r] = Ws[o*256 + k]; }
    else if (id < 196608)  { int r = id - 131072, k = r >> 8, o = r & 255; g_WTh[r] = Wh[o*256 + k]; }
    else if (id < 229376)  { int r = id - 196608, k = r >> 7, o = r & 127; g_WTp[r] = Wp[o*256 + k]; }
    else if (id < 262144)  { int r = id - 229376, k = r >> 7, o = r & 127; g_WTu[r] = Wu[o*256 + k]; }
}

// smem float counts
#define SM_EMB    (NSEQ*EDIM)     // 16384
#define SM_STACK  (SSZ*SDIM)      // 16384
#define SMEM_FLOATS (SM_EMB + SM_STACK + 256/*inp*/ + 256/*hid*/ + 256/*ihid*/ \
                     + 128/*coef*/ + 128/*uval*/ + 128/*push*/ + 128/*empty*/ \
                     + 256/*bI*/ + 256/*bH*/ + 1024/*partI*/ + 1024/*partH*/ + 8/*scal*/)
#define SMEM_BYTES (SMEM_FLOATS * 4)

__global__ __launch_bounds__(256, 1)
void srnn_kernel(const int* __restrict__ inputs, const float* __restrict__ emb_W,
                 const float* __restrict__ b_e2h, const float* __restrict__ b_s2h,
                 const float* __restrict__ b_h2h,
                 const float* __restrict__ W_h2i, const float* __restrict__ b_h2i,
                 const float* __restrict__ b_h2s, const float* __restrict__ b_s2u,
                 const float* __restrict__ empty_elem, float* __restrict__ out)
{
    extern __shared__ float sm[];
    float* s_emb   = sm;                       // [64][256]
    float* s_stack = s_emb + SM_EMB;           // [128][128]
    float* s_inp   = s_stack + SM_STACK;       // 256
    float* s_hid   = s_inp + 256;              // 256
    float* s_ihid  = s_hid + 256;              // 256
    float* s_coef  = s_ihid + 256;             // 128
    float* s_uval  = s_coef + 128;             // 128
    float* s_push  = s_uval + 128;             // 128
    float* s_empty = s_push + 128;             // 128
    float* s_bI    = s_empty + 128;            // 256 (b_e2h + b_s2h)
    float* s_bH    = s_bI + 256;               // 256 (b_h2h)
    float* s_partI = s_bH + 256;               // [4][256]
    float* s_partH = s_partI + 1024;           // [4][256]
    float* s_scal  = s_partH + 1024;           // 8

    const int tid = threadIdx.x;
    const int b   = blockIdx.x;

    // ---- init ----
    for (int idx = tid; idx < NSEQ*EDIM; idx += 256) {
        int r = idx >> 8, d = idx & 255;
        s_emb[idx] = emb_W[inputs[r*BSZ + b]*EDIM + d];
    }
    for (int idx = tid; idx < SSZ*SDIM; idx += 256)
        s_stack[idx] = empty_elem[idx & 127];
    s_hid[tid] = 0.f;
    if (tid < 128) { s_coef[tid] = (tid == 0) ? 1.f : 0.f; s_empty[tid] = empty_elem[tid]; }
    s_bI[tid] = b_e2h[tid] + b_s2h[tid];
    s_bH[tid] = b_h2h[tid];
    __syncthreads();

    const int o4   = tid & 63;   // output float4 index (big GEMV)
    const int ks   = tid >> 6;   // k-slice (big GEMV)
    const int o2   = tid & 127;  // output index (small GEMVs)
    const int kh   = tid >> 7;   // k-half (small GEMVs)
    const int j    = tid & 127;  // stack column
    const int h    = tid >> 7;   // stack row-half
    const int wid  = tid >> 5, lane = tid & 31;

    const float4* WTe4 = (const float4*)g_WTe;
    const float4* WTs4 = (const float4*)g_WTs;
    const float4* WTh4 = (const float4*)g_WTh;

    for (int t = 0; t < T_STEPS; t++) {
        // ---- phase 1: inp[d] = sum_k coef[t-k] * emb[k][d] ----
        {
            int kmax = (t < 63) ? t : 63;
            float acc = 0.f;
            for (int k = 0; k <= kmax; k++)
                acc += s_coef[t - k] * s_emb[k*EDIM + tid];
            s_inp[tid] = acc;
        }
        __syncthreads();

        // ---- phase 2: big GEMV: ihid_pre = We*inp + Ws*tops, hpre = Wh*hid ----
        {
            float4 aI = make_float4(0.f,0.f,0.f,0.f);
            float4 aH = make_float4(0.f,0.f,0.f,0.f);
            const int kbase = ks * 64;
            #pragma unroll 4
            for (int kk = 0; kk < 64; kk++) {
                int k = kbase + kk;
                float xi = s_inp[k];
                float xt = s_stack[k];   // tops = stack rows 0..1 flat
                float xh = s_hid[k];
                float4 we = WTe4[k*64 + o4];
                float4 ws = WTs4[k*64 + o4];
                float4 wh = WTh4[k*64 + o4];
                aI.x += xi*we.x + xt*ws.x;  aI.y += xi*we.y + xt*ws.y;
                aI.z += xi*we.z + xt*ws.z;  aI.w += xi*we.w + xt*ws.w;
                aH.x += xh*wh.x;  aH.y += xh*wh.y;
                aH.z += xh*wh.z;  aH.w += xh*wh.w;
            }
            ((float4*)s_partI)[ks*64 + o4] = aI;
            ((float4*)s_partH)[ks*64 + o4] = aH;
        }
        __syncthreads();

        // ---- phase 3: reduce partials, hid update, write outputs ----
        {
            float vI = s_partI[tid] + s_partI[256+tid] + s_partI[512+tid] + s_partI[768+tid] + s_bI[tid];
            float vH = s_partH[tid] + s_partH[256+tid] + s_partH[512+tid] + s_partH[768+tid] + s_bH[tid];
            float hn = vI + vH;  hn = hn > 0.f ? hn : 0.f;
            s_ihid[tid] = vI;
            s_hid[tid]  = hn;           // old hid fully consumed in phase 2
            out[OUT_OUTPUTS + (t*BSZ + b)*HDIM + tid] = hn;
        }
        __syncthreads();

        // ---- phase 4: inst (3 dots), u_val & push GEMVs ----
        if (wid < 3) {
            float a = 0.f;
            const float* wr = W_h2i + wid*256;
            for (int k = lane; k < 256; k += 32) a += s_ihid[k] * wr[k];
            #pragma unroll
            for (int off = 16; off; off >>= 1) a += __shfl_down_sync(0xffffffff, a, off);
            if (lane == 0) s_scal[wid] = a + b_h2i[wid];
        }
        {
            float aU = 0.f, aP = 0.f;
            const int kb = kh * 128;
            #pragma unroll 4
            for (int kk = 0; kk < 128; kk++) {
                int k = kb + kk;
                aU += s_stack[k] * g_WTu[k*128 + o2];   // tops @ W_s2u^T
                aP += s_hid[k]   * g_WTp[k*128 + o2];   // hid_new @ W_h2s^T
            }
            s_partI[tid] = aU;
            s_partH[tid] = aP;
        }
        __syncthreads();
        if (tid == 0) {
            float i0 = s_scal[0], i1 = s_scal[1], i2 = s_scal[2];
            float m  = fmaxf(i0, i1);
            float e0 = expf(i0 - m), e1 = expf(i1 - m);
            float inv = 1.f / (e0 + e1);
            float act0 = e0 * inv, act1 = e1 * inv;
            float sp = fmaxf(i2, 0.f) + log1pf(expf(-fabsf(i2)));
            float g  = 1.f + sp;
            float a0 = powf(act0, g), a1 = powf(act1, g);
            float s  = a0 + a1 + 1e-16f;
            float pp = a0 / s, pq = a1 / s;
            s_scal[3] = pp;  s_scal[4] = pq;
            out[OUT_ACTS + (t*BSZ + b)*2 + 0] = pp;
            out[OUT_ACTS + (t*BSZ + b)*2 + 1] = pq;
        }
        if (tid < 128) {
            float u  = s_partI[tid] + s_partI[128 + tid] + b_s2u[tid];
            float pv = s_partH[tid] + s_partH[128 + tid] + b_h2s[tid];
            s_uval[tid] = u  > 0.f ? u  : 0.f;
            s_push[tid] = pv > 0.f ? pv : 0.f;
        }
        __syncthreads();

        // ---- phase 5: stack recurrence (in place), coef update, top output ----
        {
            const float pp = s_scal[3], pq = s_scal[4];
            float c = 0.f, cmv = 0.f;
            if (tid < 128) { c = s_coef[tid]; cmv = tid ? s_coef[tid - 1] : 0.f; }
            // boundary snapshots across the two row-halves
            float bnd = h ? s_stack[63*SDIM + j] : s_stack[64*SDIM + j];
            __syncthreads();
            if (tid < 128) s_coef[tid] = pp*c + pq*cmv;

            float prev = h ? bnd : 0.f;       // old[i-1] carried
            const int ibase = h * 64;
            #pragma unroll 8
            for (int ii = 0; ii < 64; ii++) {
                int i = ibase + ii;
                float cur = s_stack[i*SDIM + j];   // old[i], read before overwrite
                float nv;
                if (i == 0) {
                    nv = pp * s_push[j] + pq * s_uval[j];
                } else if (i == 127) {
                    nv = pp * prev + pq * s_empty[j];
                } else {
                    float nxt = (i == 63) ? bnd : s_stack[(i+1)*SDIM + j];
                    nv = pp * prev + pq * nxt;
                }
                s_stack[i*SDIM + j] = nv;
                prev = cur;
                if (i == 0) out[OUT_TOP + (t*BSZ + b)*SDIM + j] = nv;
            }
        }
        __syncthreads();
    }

    // ---- final outputs ----
    out[OUT_HID + b*HDIM + tid] = s_hid[tid];
    for (int idx = tid; idx < SSZ*SDIM; idx += 256)
        out[OUT_STACK + b*SSZ*SDIM + idx] = s_stack[idx];
}

extern "C" void kernel_launch(void* const* d_in, const int* in_sizes, int n_in,
                              void* d_out, int out_size)
{
    const int*   inputs = (const int*)  d_in[0];
    const float* emb_W  = (const float*)d_in[1];
    const float* W_e2h  = (const float*)d_in[2];
    const float* b_e2h  = (const float*)d_in[3];
    const float* W_s2h  = (const float*)d_in[4];
    const float* b_s2h  = (const float*)d_in[5];
    const float* W_h2h  = (const float*)d_in[6];
    const float* b_h2h  = (const float*)d_in[7];
    const float* W_h2i  = (const float*)d_in[8];
    const float* b_h2i  = (const float*)d_in[9];
    const float* W_h2s  = (const float*)d_in[10];
    const float* b_h2s  = (const float*)d_in[11];
    const float* W_s2u  = (const float*)d_in[12];
    const float* b_s2u  = (const float*)d_in[13];
    const float* empty  = (const float*)d_in[14];
    float* out = (float*)d_out;

    prep_kernel<<<1024, 256>>>(W_e2h, W_s2h, W_h2h, W_h2s, W_s2u);

    cudaFuncSetAttribute(srnn_kernel, cudaFuncAttributeMaxDynamicSharedMemorySize, SMEM_BYTES);
    srnn_kernel<<<BSZ, 256, SMEM_BYTES>>>(inputs, emb_W, b_e2h, b_s2h, b_h2h,
                                          W_h2i, b_h2i, b_h2s, b_s2u, empty, out);
}

// round 6
// speedup vs baseline: 2.6653x; 2.6653x over previous
#include <cuda_runtime.h>
#include <cstdint>

// ---------------------------------------------------------------------------
// EncoderSRNN on GB300: 4-CTA cluster per batch element (32 clusters = 128
// CTAs ≈ full chip). Each CTA owns 64/256 hidden outputs and 32/128 stack
// columns; hid/ihid/tops exchanged via DSMEM + barrier.cluster (3 per step).
// Weights pre-transposed (k-major) for coalesced float4 GEMV loads.
// Buffer recurrence replaced by commuting-shift coefficient vector.
// ---------------------------------------------------------------------------

#define T_STEPS 127
#define NSEQ    64
#define BSZ     32
#define HDIM    256
#define SDIM    128
#define SSZ     128
#define CSIZE   4

#define OUT_OUTPUTS 0
#define OUT_HID     (T_STEPS*BSZ*HDIM)               // 1040384
#define OUT_STACK   (OUT_HID + BSZ*HDIM)             // 1048576
#define OUT_ACTS    (OUT_STACK + BSZ*SSZ*SDIM)       // 1572864
#define OUT_TOP     (OUT_ACTS + T_STEPS*BSZ*2)       // 1580992

// Transposed weights: WT[k][o] = W[o][k]
__device__ __align__(16) float g_WTe[256*256];
__device__ __align__(16) float g_WTs[256*256];
__device__ __align__(16) float g_WTh[256*256];
__device__ __align__(16) float g_WTp[256*128];
__device__ __align__(16) float g_WTu[256*128];

__global__ void prep_kernel(const float* __restrict__ We, const float* __restrict__ Ws,
                            const float* __restrict__ Wh, const float* __restrict__ Wp,
                            const float* __restrict__ Wu) {
    int id = blockIdx.x * blockDim.x + threadIdx.x;   // 262144 total
    if (id < 65536)        { int k = id >> 8,           o = id & 255;  g_WTe[id]          = We[o*256 + k]; }
    else if (id < 131072)  { int r = id - 65536,  k = r >> 8, o = r & 255; g_WTs[r] = Ws[o*256 + k]; }
    else if (id < 196608)  { int r = id - 131072, k = r >> 8, o = r & 255; g_WTh[r] = Wh[o*256 + k]; }
    else if (id < 229376)  { int r = id - 196608, k = r >> 7, o = r & 127; g_WTp[r] = Wp[o*256 + k]; }
    else if (id < 262144)  { int r = id - 229376, k = r >> 7, o = r & 127; g_WTu[r] = Wu[o*256 + k]; }
}

// ---- smem layout (floats) ----
#define F_EMB   0            // 64*256 = 16384
#define F_STK   16384        // 2 * 128*32 = 8192
#define F_INP   24576        // 256
#define F_HID   24832        // 256
#define F_IHID  25088        // 256
#define F_TOPS  25344        // 256
#define F_COEF  25600        // 128
#define F_BI    25728        // 64
#define F_BH    25792        // 64
#define F_BU    25856        // 32
#define F_BP    25888        // 32
#define F_EMP   25920        // 32
#define F_PUSH  25952        // 32
#define F_UVAL  25984        // 32
#define F_PI    26016        // 1024 (aliased by pP in phase after sync2)
#define F_PH    27040        // 1024
#define F_PU    28064        // 1024
#define F_SCAL  29088        // 16
#define SMEM_FLOATS 29104
#define SMEM_BYTES  (SMEM_FLOATS*4)

__device__ __forceinline__ uint32_t smem_u32(const void* p) {
    uint32_t a;
    asm("{ .reg .u64 t; cvta.to.shared.u64 t, %1; cvt.u32.u64 %0, t; }" : "=r"(a) : "l"(p));
    return a;
}
__device__ __forceinline__ void st_cluster_f32(uint32_t laddr, uint32_t rank, float v) {
    uint32_t ra;
    asm("mapa.shared::cluster.u32 %0, %1, %2;" : "=r"(ra) : "r"(laddr), "r"(rank));
    asm volatile("st.shared::cluster.f32 [%0], %1;" :: "r"(ra), "f"(v) : "memory");
}
#define CLUSTER_SYNC() do { \
    asm volatile("barrier.cluster.arrive.aligned;" ::: "memory"); \
    asm volatile("barrier.cluster.wait.aligned;"   ::: "memory"); \
} while (0)

__global__ __launch_bounds__(256, 1) __cluster_dims__(CSIZE, 1, 1)
void srnn_kernel(const int* __restrict__ inputs, const float* __restrict__ emb_W,
                 const float* __restrict__ b_e2h, const float* __restrict__ b_s2h,
                 const float* __restrict__ b_h2h,
                 const float* __restrict__ W_h2i, const float* __restrict__ b_h2i,
                 const float* __restrict__ b_h2s, const float* __restrict__ b_s2u,
                 const float* __restrict__ empty_elem, float* __restrict__ out)
{
    extern __shared__ float sm[];
    float* s_emb  = sm + F_EMB;
    float* s_stk  = sm + F_STK;
    float* s_inp  = sm + F_INP;
    float* s_hid  = sm + F_HID;
    float* s_ihid = sm + F_IHID;
    float* s_tops = sm + F_TOPS;
    float* s_coef = sm + F_COEF;
    float* s_bI   = sm + F_BI;
    float* s_bH   = sm + F_BH;
    float* s_bu   = sm + F_BU;
    float* s_bp   = sm + F_BP;
    float* s_emp  = sm + F_EMP;
    float* s_push = sm + F_PUSH;
    float* s_uval = sm + F_UVAL;
    float* s_pI   = sm + F_PI;
    float* s_pH   = sm + F_PH;
    float* s_pU   = sm + F_PU;
    float* s_pP   = sm + F_PI;   // alias: pI free after pre-sync1 reduce
    float* s_scal = sm + F_SCAL;

    const int tid = threadIdx.x;
    uint32_t r;
    asm("mov.u32 %0, %%cluster_ctarank;" : "=r"(r));
    const int b = blockIdx.x >> 2;

    const uint32_t a_hid  = smem_u32(s_hid);
    const uint32_t a_ihid = smem_u32(s_ihid);
    const uint32_t a_tops = smem_u32(s_tops);

    // ---- init ----
    for (int idx = tid; idx < NSEQ*256; idx += 256) {
        int row = idx >> 8, d = idx & 255;
        s_emb[idx] = emb_W[inputs[row*BSZ + b]*256 + d];
    }
    for (int idx = tid; idx < 128*32; idx += 256)
        s_stk[idx] = empty_elem[r*32 + (idx & 31)];      // buffer 0
    s_hid[tid]  = 0.f;
    s_tops[tid] = empty_elem[tid & 127];
    if (tid < 128) s_coef[tid] = (tid == 0) ? 1.f : 0.f;
    if (tid < 64)  { s_bI[tid] = b_e2h[r*64 + tid] + b_s2h[r*64 + tid]; s_bH[tid] = b_h2h[r*64 + tid]; }
    if (tid < 32)  { s_emp[tid] = empty_elem[r*32 + tid]; s_bu[tid] = b_s2u[r*32 + tid]; s_bp[tid] = b_h2s[r*32 + tid]; }
    if (tid < 3)   s_scal[5 + tid] = b_h2i[tid];
    __syncthreads();

    // thread roles
    const int o4  = tid & 15, ks  = tid >> 4;    // big GEMV: 16 float4 outs x 16 k-slices
    const int og  = (int)r*16 + o4;
    const int o8  = tid & 7,  ksp = tid >> 3;    // small GEMV: 8 float4 outs x 32 k-slices
    const int ogp = (int)r*8 + o8;
    const int j32 = tid & 31, grp = tid >> 5;    // stack: 32 cols x 8 row-groups of 16
    const int wid = tid >> 5, lane = tid & 31;

    const float4* WTe4 = (const float4*)g_WTe;
    const float4* WTs4 = (const float4*)g_WTs;
    const float4* WTh4 = (const float4*)g_WTh;
    const float4* WTp4 = (const float4*)g_WTp;
    const float4* WTu4 = (const float4*)g_WTu;

    int cur = 0;

    for (int t = 0; t < T_STEPS; t++) {
        // ---- inp[d] = sum_k coef[t-k]*emb[k][d] (redundant per CTA) ----
        {
            int kmax = (t < 63) ? t : 63;
            float acc = 0.f;
            for (int k = 0; k <= kmax; k++)
                acc = fmaf(s_coef[t - k], s_emb[k*256 + tid], acc);
            s_inp[tid] = acc;
        }
        __syncthreads();

        // ---- big GEMV partials (owned 64 outputs) + u-GEMV partials ----
        {
            float4 aI = make_float4(0.f,0.f,0.f,0.f);
            float4 aH = make_float4(0.f,0.f,0.f,0.f);
            const int kb = ks*16;
            #pragma unroll
            for (int kk = 0; kk < 16; kk++) {
                int k = kb + kk;
                float xi = s_inp[k], xt = s_tops[k], xh = s_hid[k];
                float4 we = WTe4[k*64 + og];
                float4 ws = WTs4[k*64 + og];
                float4 wh = WTh4[k*64 + og];
                aI.x = fmaf(xi,we.x,fmaf(xt,ws.x,aI.x));
                aI.y = fmaf(xi,we.y,fmaf(xt,ws.y,aI.y));
                aI.z = fmaf(xi,we.z,fmaf(xt,ws.z,aI.z));
                aI.w = fmaf(xi,we.w,fmaf(xt,ws.w,aI.w));
                aH.x = fmaf(xh,wh.x,aH.x); aH.y = fmaf(xh,wh.y,aH.y);
                aH.z = fmaf(xh,wh.z,aH.z); aH.w = fmaf(xh,wh.w,aH.w);
            }
            ((float4*)s_pI)[ks*16 + o4] = aI;
            ((float4*)s_pH)[ks*16 + o4] = aH;

            float4 aU = make_float4(0.f,0.f,0.f,0.f);
            const int kbp = ksp*8;
            #pragma unroll
            for (int kk = 0; kk < 8; kk++) {
                int k = kbp + kk;
                float xt = s_tops[k];
                float4 wu = WTu4[k*32 + ogp];
                aU.x = fmaf(xt,wu.x,aU.x); aU.y = fmaf(xt,wu.y,aU.y);
                aU.z = fmaf(xt,wu.z,aU.z); aU.w = fmaf(xt,wu.w,aU.w);
            }
            ((float4*)s_pU)[ksp*8 + o8] = aU;
        }
        __syncthreads();

        // ---- reduce big partials -> new hid/ihid chunk (registers) ----
        float vI = 0.f, hn = 0.f;
        if (tid < 64) {
            float sI = s_bI[tid], sH = s_bH[tid];
            #pragma unroll
            for (int s = 0; s < 16; s++) { sI += s_pI[s*64 + tid]; sH += s_pH[s*64 + tid]; }
            vI = sI;
            hn = sI + sH; hn = hn > 0.f ? hn : 0.f;
            out[OUT_OUTPUTS + (t*BSZ + b)*HDIM + (int)r*64 + tid] = hn;
        }

        CLUSTER_SYNC();   // all CTAs done reading old hid/tops/inp

        // ---- broadcast owned hid/ihid chunk to all 4 CTAs ----
        if (tid < 64) {
            uint32_t off = ((uint32_t)r*64 + (uint32_t)tid)*4u;
            #pragma unroll
            for (uint32_t pr = 0; pr < CSIZE; pr++) {
                st_cluster_f32(a_hid  + off, pr, hn);
                st_cluster_f32(a_ihid + off, pr, vI);
            }
        }

        CLUSTER_SYNC();   // new hid/ihid visible everywhere

        // ---- inst dots (warps 0-2), push-GEMV partials ----
        if (wid < 3) {
            float a = 0.f;
            const float* wr = W_h2i + wid*256;
            #pragma unroll
            for (int it = 0; it < 8; it++) {
                int k = lane + it*32;
                a = fmaf(s_ihid[k], wr[k], a);
            }
            #pragma unroll
            for (int off = 16; off; off >>= 1) a += __shfl_down_sync(0xffffffff, a, off);
            if (lane == 0) s_scal[wid] = a + s_scal[5 + wid];
        }
        {
            float4 aP = make_float4(0.f,0.f,0.f,0.f);
            const int kbp = ksp*8;
            #pragma unroll
            for (int kk = 0; kk < 8; kk++) {
                int k = kbp + kk;
                float xh = s_hid[k];
                float4 wp = WTp4[k*32 + ogp];
                aP.x = fmaf(xh,wp.x,aP.x); aP.y = fmaf(xh,wp.y,aP.y);
                aP.z = fmaf(xh,wp.z,aP.z); aP.w = fmaf(xh,wp.w,aP.w);
            }
            ((float4*)s_pP)[ksp*8 + o8] = aP;
        }
        float cc = 0.f, cm = 0.f;
        if (tid < 128) { cc = s_coef[tid]; cm = tid ? s_coef[tid-1] : 0.f; }
        __syncthreads();

        if (tid == 0) {
            float i0 = s_scal[0], i1 = s_scal[1], i2 = s_scal[2];
            float m  = fmaxf(i0, i1);
            float e0 = expf(i0 - m), e1 = expf(i1 - m);
            float inv = 1.f / (e0 + e1);
            float act0 = e0*inv, act1 = e1*inv;
            float sp = fmaxf(i2, 0.f) + log1pf(expf(-fabsf(i2)));
            float g  = 1.f + sp;
            float a0 = powf(act0, g), a1 = powf(act1, g);
            float s  = a0 + a1 + 1e-16f;
            float pp = a0 / s, pq = a1 / s;
            s_scal[3] = pp; s_scal[4] = pq;
            if (r == 0) {
                out[OUT_ACTS + (t*BSZ + b)*2 + 0] = pp;
                out[OUT_ACTS + (t*BSZ + b)*2 + 1] = pq;
            }
        }
        if (tid < 32) {
            float u = s_bu[tid], pv = s_bp[tid];
            #pragma unroll
            for (int s = 0; s < 32; s++) { u += s_pU[s*32 + tid]; pv += s_pP[s*32 + tid]; }
            s_uval[tid] = u  > 0.f ? u  : 0.f;
            s_push[tid] = pv > 0.f ? pv : 0.f;
        }
        __syncthreads();

        // ---- coef update + stack recurrence (owned 32 cols, double-buffer) ----
        {
            const float pp = s_scal[3], pq = s_scal[4];
            if (tid < 128) s_coef[tid] = fmaf(pp, cc, pq*cm);

            const float* so = s_stk + cur*4096;
            float*       sn = s_stk + (1-cur)*4096;
            const int i0 = grp*16;
            float a_prev = (i0 == 0)   ? 0.f : so[(i0-1)*32 + j32];
            float a_cur  = so[i0*32 + j32];
            #pragma unroll
            for (int ii = 0; ii < 16; ii++) {
                int i = i0 + ii;
                float a_next = (i == 127) ? 0.f : so[(i+1)*32 + j32];
                float nv;
                if (i == 0)        nv = fmaf(pp, s_push[j32], pq*s_uval[j32]);
                else if (i == 127) nv = fmaf(pp, a_prev,      pq*s_emp[j32]);
                else               nv = fmaf(pp, a_prev,      pq*a_next);
                sn[i*32 + j32] = nv;
                if (i <= 1) {
                    if (i == 0)
                        out[OUT_TOP + (t*BSZ + b)*SDIM + (int)r*32 + j32] = nv;
                    uint32_t off = ((uint32_t)i*128u + (uint32_t)r*32u + (uint32_t)j32)*4u;
                    #pragma unroll
                    for (uint32_t pr = 0; pr < CSIZE; pr++)
                        st_cluster_f32(a_tops + off, pr, nv);
                }
                a_prev = a_cur;
                a_cur  = a_next;
            }
        }
        cur ^= 1;

        CLUSTER_SYNC();   // new tops visible for next step
    }

    // ---- final outputs ----
    if (tid < 64) out[OUT_HID + b*HDIM + (int)r*64 + tid] = s_hid[(int)r*64 + tid];
    const float* sf = s_stk + cur*4096;
    for (int idx = tid; idx < 128*32; idx += 256) {
        int i = idx >> 5, j = idx & 31;
        out[OUT_STACK + b*SSZ*SDIM + i*SDIM + (int)r*32 + j] = sf[idx];
    }
}

extern "C" void kernel_launch(void* const* d_in, const int* in_sizes, int n_in,
                              void* d_out, int out_size)
{
    const int*   inputs = (const int*)  d_in[0];
    const float* emb_W  = (const float*)d_in[1];
    const float* W_e2h  = (const float*)d_in[2];
    const float* b_e2h  = (const float*)d_in[3];
    const float* W_s2h  = (const float*)d_in[4];
    const float* b_s2h  = (const float*)d_in[5];
    const float* W_h2h  = (const float*)d_in[6];
    const float* b_h2h  = (const float*)d_in[7];
    const float* W_h2i  = (const float*)d_in[8];
    const float* b_h2i  = (const float*)d_in[9];
    const float* W_h2s  = (const float*)d_in[10];
    const float* b_h2s  = (const float*)d_in[11];
    const float* W_s2u  = (const float*)d_in[12];
    const float* b_s2u  = (const float*)d_in[13];
    const float* empty  = (const float*)d_in[14];
    float* out = (float*)d_out;

    prep_kernel<<<1024, 256>>>(W_e2h, W_s2h, W_h2h, W_h2s, W_s2u);

    static int configured = 0;
    if (!configured) {
        cudaFuncSetAttribute(srnn_kernel, cudaFuncAttributeMaxDynamicSharedMemorySize, SMEM_BYTES);
        configured = 1;
    }
    srnn_kernel<<<BSZ*CSIZE, 256, SMEM_BYTES>>>(inputs, emb_W, b_e2h, b_s2h, b_h2h,
                                                W_h2i, b_h2i, b_h2s, b_s2u, empty, out);
}

// round 8
// speedup vs baseline: 2.7298x; 1.0242x over previous
#include <cuda_runtime.h>
#include <cstdint>

// ---------------------------------------------------------------------------
// EncoderSRNN on GB300: 4-CTA cluster per batch element, 512 threads/CTA.
// Double-buffered hid/tops (2 cluster syncs/step). inst + push computed as
// per-CTA partials before the mid sync (scalar/32-float DSMEM exchange).
// WTu/WTp slices + W_h2i resident in smem; big-GEMV weights streamed from L2.
// ---------------------------------------------------------------------------

#define T_STEPS 127
#define NSEQ    64
#define BSZ     32
#define HDIM    256
#define SDIM    128
#define SSZ     128
#define CSIZE   4
#define NTHR    512

#define OUT_OUTPUTS 0
#define OUT_HID     (T_STEPS*BSZ*HDIM)               // 1040384
#define OUT_STACK   (OUT_HID + BSZ*HDIM)             // 1048576
#define OUT_ACTS    (OUT_STACK + BSZ*SSZ*SDIM)       // 1572864
#define OUT_TOP     (OUT_ACTS + T_STEPS*BSZ*2)       // 1580992

// Transposed weights: WT[k][o] = W[o][k]
__device__ __align__(16) float g_WTe[256*256];
__device__ __align__(16) float g_WTs[256*256];
__device__ __align__(16) float g_WTh[256*256];
__device__ __align__(16) float g_WTp[256*128];
__device__ __align__(16) float g_WTu[256*128];

__global__ void prep_kernel(const float* __restrict__ We, const float* __restrict__ Ws,
                            const float* __restrict__ Wh, const float* __restrict__ Wp,
                            const float* __restrict__ Wu) {
    int id = blockIdx.x * blockDim.x + threadIdx.x;   // 262144 total
    if (id < 65536)        { int k = id >> 8,           o = id & 255;  g_WTe[id]          = We[o*256 + k]; }
    else if (id < 131072)  { int r = id - 65536,  k = r >> 8, o = r & 255; g_WTs[r] = Ws[o*256 + k]; }
    else if (id < 196608)  { int r = id - 131072, k = r >> 8, o = r & 255; g_WTh[r] = Wh[o*256 + k]; }
    else if (id < 229376)  { int r = id - 196608, k = r >> 7, o = r & 127; g_WTp[r] = Wp[o*256 + k]; }
    else if (id < 262144)  { int r = id - 229376, k = r >> 7, o = r & 127; g_WTu[r] = Wu[o*256 + k]; }
}

// ---- smem layout (float offsets) ----
#define F_EMB    0        // 16384  [64][256]
#define F_STK    16384    // 8192   [2][128][32]
#define F_WTU    24576    // 8192   [256][32]  (owned 32 u-cols)
#define F_WTP    32768    // 8192   [64][128]  (owned 64 k-rows, all 128 cols)
#define F_INPP   40960    // 512    [2][256]
#define F_HID    41472    // 512    [2][256]
#define F_TOPS   41984    // 512    [2][256]
#define F_HIDLOC 42496    // 64
#define F_IHLOC  42560    // 64
#define F_COEF   42624    // 128
#define F_BI     42752    // 64
#define F_BH     42816    // 64
#define F_BU     42880    // 32
#define F_BP     42912    // 32
#define F_EMP    42944    // 32
#define F_PUSH   42976    // 32
#define F_UVAL   43008    // 32
#define F_BIAS   43040    // 4
#define F_SCAL   43044    // 12
#define F_WHI    43056    // 768   [3][256]
#define F_PI     43824    // 2048  [32][64]   (aliased by push partials [16][128])
#define F_PH     45872    // 2048  [32][64]
#define F_PU     47920    // 2048  [64][32]
#define F_PPART  49968    // 128   [4][32]
#define F_INSTP  50096    // 16    [4][4]
#define SMEM_FLOATS 50112
#define SMEM_BYTES  (SMEM_FLOATS*4)   // 200448

__device__ __forceinline__ uint32_t smem_u32(const void* p) {
    uint32_t a;
    asm("{ .reg .u64 t; cvta.to.shared.u64 t, %1; cvt.u32.u64 %0, t; }" : "=r"(a) : "l"(p));
    return a;
}
__device__ __forceinline__ void st_cluster_f32(uint32_t laddr, uint32_t rank, float v) {
    uint32_t ra;
    asm("mapa.shared::cluster.u32 %0, %1, %2;" : "=r"(ra) : "r"(laddr), "r"(rank));
    asm volatile("st.shared::cluster.f32 [%0], %1;" :: "r"(ra), "f"(v) : "memory");
}
#define CLUSTER_SYNC() do { \
    asm volatile("barrier.cluster.arrive.aligned;" ::: "memory"); \
    asm volatile("barrier.cluster.wait.aligned;"   ::: "memory"); \
} while (0)

__global__ __launch_bounds__(NTHR, 1) __cluster_dims__(CSIZE, 1, 1)
void srnn_kernel(const int* __restrict__ inputs, const float* __restrict__ emb_W,
                 const float* __restrict__ b_e2h, const float* __restrict__ b_s2h,
                 const float* __restrict__ b_h2h,
                 const float* __restrict__ W_h2i, const float* __restrict__ b_h2i,
                 const float* __restrict__ b_h2s, const float* __restrict__ b_s2u,
                 const float* __restrict__ empty_elem, float* __restrict__ out)
{
    extern __shared__ float sm[];
    float* s_emb   = sm + F_EMB;
    float* s_stk   = sm + F_STK;
    float* s_wtu   = sm + F_WTU;
    float* s_wtp   = sm + F_WTP;
    float* s_inpp  = sm + F_INPP;
    float* s_hid   = sm + F_HID;
    float* s_tops  = sm + F_TOPS;
    float* s_hidloc= sm + F_HIDLOC;
    float* s_ihloc = sm + F_IHLOC;
    float* s_coef  = sm + F_COEF;
    float* s_bI    = sm + F_BI;
    float* s_bH    = sm + F_BH;
    float* s_bu    = sm + F_BU;
    float* s_bp    = sm + F_BP;
    float* s_emp   = sm + F_EMP;
    float* s_push  = sm + F_PUSH;
    float* s_uval  = sm + F_UVAL;
    float* s_bias  = sm + F_BIAS;
    float* s_scal  = sm + F_SCAL;
    float* s_whi   = sm + F_WHI;
    float* s_pI    = sm + F_PI;
    float* s_pH    = sm + F_PH;
    float* s_pU    = sm + F_PU;
    float* s_pP    = sm + F_PI;   // alias: pI dead after phase-C reduce
    float* s_ppart = sm + F_PPART;
    float* s_instp = sm + F_INSTP;

    const int tid = threadIdx.x;
    uint32_t r;
    asm("mov.u32 %0, %%cluster_ctarank;" : "=r"(r));
    const int b = blockIdx.x >> 2;
    const int ri = (int)r;

    const uint32_t a_hid   = smem_u32(s_hid);
    const uint32_t a_tops  = smem_u32(s_tops);
    const uint32_t a_ppart = smem_u32(s_ppart);
    const uint32_t a_instp = smem_u32(s_instp);

    // ---- init ----
    for (int idx = tid; idx < NSEQ*256; idx += NTHR) {
        int row = idx >> 8, d = idx & 255;
        s_emb[idx] = emb_W[inputs[row*BSZ + b]*256 + d];
    }
    for (int idx = tid; idx < 128*32; idx += NTHR)
        s_stk[idx] = empty_elem[ri*32 + (idx & 31)];          // stack buf 0
    for (int idx = tid; idx < 256*32; idx += NTHR) {          // owned u-weights
        int k = idx >> 5, c = idx & 31;
        s_wtu[idx] = g_WTu[k*128 + ri*32 + c];
    }
    for (int idx = tid; idx < 64*128; idx += NTHR) {          // owned push-weight rows
        int kl = idx >> 7, c = idx & 127;
        s_wtp[idx] = g_WTp[(ri*64 + kl)*128 + c];
    }
    for (int idx = tid; idx < 768; idx += NTHR) s_whi[idx] = W_h2i[idx];
    if (tid < 256) { s_hid[tid] = 0.f; s_tops[tid] = empty_elem[tid & 127]; }
    if (tid < 128) s_coef[tid] = (tid == 0) ? 1.f : 0.f;
    if (tid < 64)  { s_bI[tid] = b_e2h[ri*64 + tid] + b_s2h[ri*64 + tid]; s_bH[tid] = b_h2h[ri*64 + tid]; }
    if (tid < 32)  { s_emp[tid] = empty_elem[ri*32 + tid]; s_bu[tid] = b_s2u[ri*32 + tid]; s_bp[tid] = b_h2s[ri*32 + tid]; }
    if (tid < 3)   s_bias[tid] = b_h2i[tid];
    __syncthreads();
    CLUSTER_SYNC();

    const float4* WTe4 = (const float4*)g_WTe;
    const float4* WTs4 = (const float4*)g_WTs;
    const float4* WTh4 = (const float4*)g_WTh;
    const float4* wtu4 = (const float4*)s_wtu;
    const float4* wtp4 = (const float4*)s_wtp;

    const int wid = tid >> 5, lane = tid & 31;

    for (int t = 0; t < T_STEPS; t++) {
        const int rb = t & 1, wb = rb ^ 1;

        // ---- A: inp partials (two k-halves per hidden dim) ----
        {
            int d = tid & 255, hf = tid >> 8;
            int kmax = (t < 63) ? t : 63;
            float acc = 0.f;
            for (int k = hf; k <= kmax; k += 2)
                acc = fmaf(s_coef[t - k], s_emb[k*256 + d], acc);
            s_inpp[hf*256 + d] = acc;
        }
        __syncthreads();

        float cc = 0.f, cm = 0.f;
        if (tid < 128) { cc = s_coef[tid]; cm = tid ? s_coef[tid-1] : 0.f; }

        // ---- B: big GEMV partials (16 f4 outs x 32 k-slices) + u partials ----
        {
            const float* hidr = s_hid  + rb*256;
            const float* topr = s_tops + rb*256;
            const int q = tid & 15, kb = (tid >> 4)*8;
            float4 aI = make_float4(0.f,0.f,0.f,0.f);
            float4 aH = make_float4(0.f,0.f,0.f,0.f);
            #pragma unroll
            for (int kk = 0; kk < 8; kk++) {
                int k = kb + kk;
                float xi = s_inpp[k] + s_inpp[256 + k];
                float xt = topr[k], xh = hidr[k];
                float4 we = WTe4[k*64 + ri*16 + q];
                float4 ws = WTs4[k*64 + ri*16 + q];
                float4 wh = WTh4[k*64 + ri*16 + q];
                aI.x = fmaf(xi,we.x,fmaf(xt,ws.x,aI.x));
                aI.y = fmaf(xi,we.y,fmaf(xt,ws.y,aI.y));
                aI.z = fmaf(xi,we.z,fmaf(xt,ws.z,aI.z));
                aI.w = fmaf(xi,we.w,fmaf(xt,ws.w,aI.w));
                aH.x = fmaf(xh,wh.x,aH.x); aH.y = fmaf(xh,wh.y,aH.y);
                aH.z = fmaf(xh,wh.z,aH.z); aH.w = fmaf(xh,wh.w,aH.w);
            }
            ((float4*)s_pI)[(tid>>4)*16 + q] = aI;
            ((float4*)s_pH)[(tid>>4)*16 + q] = aH;

            const int q8 = tid & 7, kbu = (tid >> 3)*4;
            float4 aU = make_float4(0.f,0.f,0.f,0.f);
            #pragma unroll
            for (int kk = 0; kk < 4; kk++) {
                int k = kbu + kk;
                float xt = topr[k];
                float4 wu = wtu4[k*8 + q8];
                aU.x = fmaf(xt,wu.x,aU.x); aU.y = fmaf(xt,wu.y,aU.y);
                aU.z = fmaf(xt,wu.z,aU.z); aU.w = fmaf(xt,wu.w,aU.w);
            }
            ((float4*)s_pU)[(tid>>3)*8 + q8] = aU;
        }
        __syncthreads();

        // ---- C: reduces; hid broadcast; uval ----
        if (tid < 64) {
            float sI = s_bI[tid], sH = s_bH[tid];
            #pragma unroll
            for (int s = 0; s < 32; s++) { sI += s_pI[s*64 + tid]; sH += s_pH[s*64 + tid]; }
            float hn = sI + sH; hn = hn > 0.f ? hn : 0.f;
            s_ihloc[tid]  = sI;
            s_hidloc[tid] = hn;
            out[OUT_OUTPUTS + (t*BSZ + b)*HDIM + ri*64 + tid] = hn;
            if (t == T_STEPS-1) out[OUT_HID + b*HDIM + ri*64 + tid] = hn;
            uint32_t off = a_hid + (uint32_t)(wb*256 + ri*64 + tid)*4u;
            #pragma unroll
            for (uint32_t pr = 0; pr < CSIZE; pr++) st_cluster_f32(off, pr, hn);
        } else if (tid < 96) {
            int c = tid - 64;
            float u = s_bu[c];
            #pragma unroll
            for (int s = 0; s < 64; s++) u += s_pU[s*32 + c];
            s_uval[c] = u > 0.f ? u : 0.f;
        }
        __syncthreads();

        // ---- D: inst partial dots (warps 0-2) + push partials (all) ----
        if (wid < 3) {
            float2 w2 = *(const float2*)(s_whi + wid*256 + ri*64 + 2*lane);
            float a = fmaf(s_ihloc[2*lane], w2.x, s_ihloc[2*lane+1]*w2.y);
            #pragma unroll
            for (int off = 16; off; off >>= 1) a += __shfl_down_sync(0xffffffff, a, off);
            if (lane == 0) {
                uint32_t addr = a_instp + (uint32_t)(ri*4 + wid)*4u;
                #pragma unroll
                for (uint32_t pr = 0; pr < CSIZE; pr++) st_cluster_f32(addr, pr, a);
            }
        }
        {
            const int q = tid & 31, kb = (tid >> 5)*4;
            float4 aP = make_float4(0.f,0.f,0.f,0.f);
            #pragma unroll
            for (int kk = 0; kk < 4; kk++) {
                int kl = kb + kk;
                float xh = s_hidloc[kl];
                float4 wp = wtp4[kl*32 + q];
                aP.x = fmaf(xh,wp.x,aP.x); aP.y = fmaf(xh,wp.y,aP.y);
                aP.z = fmaf(xh,wp.z,aP.z); aP.w = fmaf(xh,wp.w,aP.w);
            }
            ((float4*)s_pP)[(tid>>5)*32 + q] = aP;
        }
        __syncthreads();

        // ---- E: push partial reduce -> DSMEM to owning peer ----
        if (tid < 128) {
            float pv = 0.f;
            #pragma unroll
            for (int s = 0; s < 16; s++) pv += s_pP[s*128 + tid];
            uint32_t peer = (uint32_t)(tid >> 5);
            int c = tid & 31;
            st_cluster_f32(a_ppart + (uint32_t)(ri*32 + c)*4u, peer, pv);
        }

        CLUSTER_SYNC();   // hid/inst/push partials visible cluster-wide

        // ---- G: softmax (tid 0) + push finalize (tid 32..63) ----
        if (tid == 0) {
            float i0 = s_instp[0] + s_instp[4]  + s_instp[8]  + s_instp[12] + s_bias[0];
            float i1 = s_instp[1] + s_instp[5]  + s_instp[9]  + s_instp[13] + s_bias[1];
            float i2 = s_instp[2] + s_instp[6]  + s_instp[10] + s_instp[14] + s_bias[2];
            float m  = fmaxf(i0, i1);
            float e0 = expf(i0 - m), e1 = expf(i1 - m);
            float inv = 1.f / (e0 + e1);
            float act0 = e0*inv, act1 = e1*inv;
            float sp = fmaxf(i2, 0.f) + log1pf(expf(-fabsf(i2)));
            float g  = 1.f + sp;
            float a0 = powf(act0, g), a1 = powf(act1, g);
            float s  = a0 + a1 + 1e-16f;
            float pp = a0 / s, pq = a1 / s;
            s_scal[0] = pp; s_scal[1] = pq;
            if (r == 0) {
                out[OUT_ACTS + (t*BSZ + b)*2 + 0] = pp;
                out[OUT_ACTS + (t*BSZ + b)*2 + 1] = pq;
            }
        } else if (tid >= 32 && tid < 64) {
            int c = tid - 32;
            float pv = s_ppart[c] + s_ppart[32+c] + s_ppart[64+c] + s_ppart[96+c] + s_bp[c];
            s_push[c] = pv > 0.f ? pv : 0.f;
        }
        __syncthreads();

        // ---- I: stack recurrence (double-buffered), coef update, tops bcast ----
        {
            const float pp = s_scal[0], pq = s_scal[1];
            if (tid < 128) s_coef[tid] = fmaf(pp, cc, pq*cm);

            const float* so = s_stk + rb*4096;
            float*       sn = s_stk + wb*4096;
            const int j = tid & 31, i0 = (tid >> 5)*8;
            float prev = i0 ? so[(i0-1)*32 + j] : 0.f;
            #pragma unroll
            for (int ii = 0; ii < 8; ii++) {
                int i = i0 + ii;
                float nxt = (i == 127) ? 0.f : so[(i+1)*32 + j];
                float nv;
                if (i == 0)        nv = fmaf(pp, s_push[j], pq*s_uval[j]);
                else if (i == 127) nv = fmaf(pp, prev,      pq*s_emp[j]);
                else               nv = fmaf(pp, prev,      pq*nxt);
                sn[i*32 + j] = nv;
                if (i == 0) out[OUT_TOP + (t*BSZ + b)*SDIM + ri*32 + j] = nv;
                if (i <= 1) {
                    uint32_t off = a_tops + (uint32_t)(wb*256 + i*128 + ri*32 + j)*4u;
                    #pragma unroll
                    for (uint32_t pr = 0; pr < CSIZE; pr++) st_cluster_f32(off, pr, nv);
                }
                prev = so[i*32 + j];
            }
        }

        CLUSTER_SYNC();   // new tops/coef/stack consistent for next step
    }

    // ---- final stack output ----
    const float* sf = s_stk + (T_STEPS & 1)*4096;
    for (int idx = tid; idx < 128*32; idx += NTHR) {
        int i = idx >> 5, j = idx & 31;
        out[OUT_STACK + b*SSZ*SDIM + i*SDIM + ri*32 + j] = sf[idx];
    }
}

extern "C" void kernel_launch(void* const* d_in, const int* in_sizes, int n_in,
                              void* d_out, int out_size)
{
    const int*   inputs = (const int*)  d_in[0];
    const float* emb_W  = (const float*)d_in[1];
    const float* W_e2h  = (const float*)d_in[2];
    const float* b_e2h  = (const float*)d_in[3];
    const float* W_s2h  = (const float*)d_in[4];
    const float* b_s2h  = (const float*)d_in[5];
    const float* W_h2h  = (const float*)d_in[6];
    const float* b_h2h  = (const float*)d_in[7];
    const float* W_h2i  = (const float*)d_in[8];
    const float* b_h2i  = (const float*)d_in[9];
    const float* W_h2s  = (const float*)d_in[10];
    const float* b_h2s  = (const float*)d_in[11];
    const float* W_s2u  = (const float*)d_in[12];
    const float* b_s2u  = (const float*)d_in[13];
    const float* empty  = (const float*)d_in[14];
    float* out = (float*)d_out;

    prep_kernel<<<1024, 256>>>(W_e2h, W_s2h, W_h2h, W_h2s, W_s2u);

    static int configured = 0;
    if (!configured) {
        cudaFuncSetAttribute(srnn_kernel, cudaFuncAttributeMaxDynamicSharedMemorySize, SMEM_BYTES);
        configured = 1;
    }
    srnn_kernel<<<BSZ*CSIZE, NTHR, SMEM_BYTES>>>(inputs, emb_W, b_e2h, b_s2h, b_h2h,
                                                 W_h2i, b_h2i, b_h2s, b_s2u, empty, out);
}